// round 2
// baseline (speedup 1.0000x reference)
#include <cuda_runtime.h>
#include <math.h>

#define NN 50000
#define NE 200000
#define H  128
#define NL 3

// ---------------- scratch (device globals: allocation-free) ----------------
__device__ float g_node_h[NN * H];     // 25.6 MB
__device__ float g_agg_edge[NN * H];   // 25.6 MB  (layer-invariant part of aggregation)
__device__ float g_agg[NN * H];        // 25.6 MB  (per-layer aggregation)
__device__ float g_edot[NE];           // dot(edge_h[e], t_edge) + b_top   (layer-invariant)
__device__ float g_a[NN];              // dot(node_h[n], t_src)
__device__ float g_c[NN];              // dot(node_h[n], t_dst)
__device__ float g_ew[NE];             // edge weights (last layer written = output)

// ---------------- helpers ----------------
__device__ __forceinline__ void red_add_v4(float* addr, float4 v) {
    asm volatile("red.global.add.v4.f32 [%0], {%1,%2,%3,%4};"
                 :: "l"(addr), "f"(v.x), "f"(v.y), "f"(v.z), "f"(v.w) : "memory");
}

__device__ __forceinline__ float warp_sum(float v) {
    #pragma unroll
    for (int o = 16; o > 0; o >>= 1) v += __shfl_xor_sync(0xffffffffu, v, o);
    return v;
}

// =====================================================================
// Node embedding: node_h[M,128] = A[M,128] @ W + b; epilogue also emits
// ga[n] = node_h[n] . t_src,  gc[n] = node_h[n] . t_dst
// 256 threads, 64 rows/block; warp -> 8 rows, lane -> 4 cols.
// =====================================================================
__global__ __launch_bounds__(256) void k_node_embed(
    const float* __restrict__ A, const float* __restrict__ W,
    const float* __restrict__ bias, const float* __restrict__ Wtop,
    float* __restrict__ C, float* __restrict__ ga, float* __restrict__ gc)
{
    constexpr int K = 128;
    extern __shared__ float sm[];
    float4* Ws4 = (float4*)sm;                 // [K][32] float4
    float4* As4 = (float4*)(sm + K * H);       // [64][K/4] float4
    const int tid  = threadIdx.x;
    const int row0 = blockIdx.x * 64;

    const float4* Wg = (const float4*)W;
    #pragma unroll 4
    for (int i = tid; i < K * H / 4; i += 256) Ws4[i] = Wg[i];

    for (int i = tid; i < 64 * (K / 4); i += 256) {
        int r = i / (K / 4), c = i % (K / 4);
        int row = row0 + r;
        float4 v = make_float4(0.f, 0.f, 0.f, 0.f);
        if (row < NN) v = ((const float4*)(A + (long)row * K))[c];
        As4[i] = v;
    }
    __syncthreads();

    const int lane = tid & 31, warp = tid >> 5;
    const int rb = warp * 8;
    float acc[8][4];
    #pragma unroll
    for (int r = 0; r < 8; r++) { acc[r][0]=0.f; acc[r][1]=0.f; acc[r][2]=0.f; acc[r][3]=0.f; }

    #pragma unroll 2
    for (int k = 0; k < K; k += 4) {
        float4 w0 = Ws4[(k + 0) * 32 + lane];
        float4 w1 = Ws4[(k + 1) * 32 + lane];
        float4 w2 = Ws4[(k + 2) * 32 + lane];
        float4 w3 = Ws4[(k + 3) * 32 + lane];
        #pragma unroll
        for (int r = 0; r < 8; r++) {
            float4 a = As4[(rb + r) * (K / 4) + (k >> 2)];
            acc[r][0] += a.x*w0.x + a.y*w1.x + a.z*w2.x + a.w*w3.x;
            acc[r][1] += a.x*w0.y + a.y*w1.y + a.z*w2.y + a.w*w3.y;
            acc[r][2] += a.x*w0.z + a.y*w1.z + a.z*w2.z + a.w*w3.z;
            acc[r][3] += a.x*w0.w + a.y*w1.w + a.z*w2.w + a.w*w3.w;
        }
    }

    float4 b4 = ((const float4*)bias)[lane];
    float4 ts = ((const float4*)Wtop)[lane];        // W_top[0:128]
    float4 td = ((const float4*)Wtop)[32 + lane];   // W_top[128:256]
    #pragma unroll
    for (int r = 0; r < 8; r++) {
        int row = row0 + rb + r;
        if (row < NN) {                               // warp-uniform
            float y0 = acc[r][0] + b4.x, y1 = acc[r][1] + b4.y;
            float y2 = acc[r][2] + b4.z, y3 = acc[r][3] + b4.w;
            ((float4*)(C + (long)row * H))[lane] = make_float4(y0, y1, y2, y3);
            float pa = warp_sum(y0*ts.x + y1*ts.y + y2*ts.z + y3*ts.w);
            float pc = warp_sum(y0*td.x + y1*td.y + y2*td.z + y3*td.w);
            if (lane == 0) { ga[row] = pa; gc[row] = pc; }
        }
    }
}

// =====================================================================
// Edge embedding (fused, edge_h never materialized):
//   edge_h = edge_features @ W_edge + b_edge          (registers only)
//   edot[e] = edge_h[e] . t_edge + b_top
//   agge[dst[e]] += edge_h[e]                         (red.v4 scatter)
// NE = 200000 is an exact multiple of 64 -> no row guards.
// =====================================================================
__global__ __launch_bounds__(256) void k_edge_embed(
    const float* __restrict__ A, const float* __restrict__ W,
    const float* __restrict__ bias, const float* __restrict__ Wtop,
    const float* __restrict__ btop, const int* __restrict__ eidx,
    float* __restrict__ edot, float* __restrict__ agge)
{
    constexpr int K = 64;
    extern __shared__ float sm[];
    float4* Ws4 = (float4*)sm;                 // [K][32] float4
    float4* As4 = (float4*)(sm + K * H);       // [64][K/4] float4
    const int tid  = threadIdx.x;
    const int row0 = blockIdx.x * 64;

    const float4* Wg = (const float4*)W;
    #pragma unroll 4
    for (int i = tid; i < K * H / 4; i += 256) Ws4[i] = Wg[i];
    #pragma unroll 4
    for (int i = tid; i < 64 * (K / 4); i += 256) {
        int r = i / (K / 4), c = i % (K / 4);
        As4[i] = ((const float4*)(A + (long)(row0 + r) * K))[c];
    }
    __syncthreads();

    const int lane = tid & 31, warp = tid >> 5;
    const int rb = warp * 8;
    float acc[8][4];
    #pragma unroll
    for (int r = 0; r < 8; r++) { acc[r][0]=0.f; acc[r][1]=0.f; acc[r][2]=0.f; acc[r][3]=0.f; }

    #pragma unroll 2
    for (int k = 0; k < K; k += 4) {
        float4 w0 = Ws4[(k + 0) * 32 + lane];
        float4 w1 = Ws4[(k + 1) * 32 + lane];
        float4 w2 = Ws4[(k + 2) * 32 + lane];
        float4 w3 = Ws4[(k + 3) * 32 + lane];
        #pragma unroll
        for (int r = 0; r < 8; r++) {
            float4 a = As4[(rb + r) * (K / 4) + (k >> 2)];
            acc[r][0] += a.x*w0.x + a.y*w1.x + a.z*w2.x + a.w*w3.x;
            acc[r][1] += a.x*w0.y + a.y*w1.y + a.z*w2.y + a.w*w3.y;
            acc[r][2] += a.x*w0.z + a.y*w1.z + a.z*w2.z + a.w*w3.z;
            acc[r][3] += a.x*w0.w + a.y*w1.w + a.z*w2.w + a.w*w3.w;
        }
    }

    float4 b4 = ((const float4*)bias)[lane];
    float4 te = ((const float4*)Wtop)[64 + lane];   // W_top[256:384]
    float bt = btop[0];
    #pragma unroll
    for (int r = 0; r < 8; r++) {
        int row = row0 + rb + r;
        float y0 = acc[r][0] + b4.x, y1 = acc[r][1] + b4.y;
        float y2 = acc[r][2] + b4.z, y3 = acc[r][3] + b4.w;
        float p = warp_sum(y0*te.x + y1*te.y + y2*te.z + y3*te.w);
        if (lane == 0) edot[row] = p + bt;
        int dst = eidx[NE + row];
        red_add_v4(agge + (long)dst * H + lane * 4, make_float4(y0, y1, y2, y3));
    }
}

// =====================================================================
// Per layer: edge weight + scatter w * node_h[src] into agg[dst]
// One warp per edge.
// =====================================================================
__global__ __launch_bounds__(256) void k_scatter(
    const float* __restrict__ node_h, const int* __restrict__ eidx,
    const float* __restrict__ ga, const float* __restrict__ gc,
    const float* __restrict__ edot, float* __restrict__ ew, float* __restrict__ agg)
{
    int e = blockIdx.x * 8 + (threadIdx.x >> 5);
    int lane = threadIdx.x & 31;
    if (e >= NE) return;
    int s = eidx[e], d = eidx[NE + e];
    float x = ga[s] + gc[d] + edot[e];
    float w = 1.f / (1.f + expf(-x));
    if (lane == 0) ew[e] = w;
    float4 h = ((const float4*)(node_h + (long)s * H))[lane];
    red_add_v4(agg + (long)d * H + lane * 4, make_float4(w*h.x, w*h.y, w*h.z, w*h.w));
}

// =====================================================================
// Node update: GEMM K=256 + bias + residual + LayerNorm + ReLU, in-place.
// Epilogue also recomputes ga/gc for the next layer's scatter.
// =====================================================================
__global__ __launch_bounds__(256) void k_gnn_update(
    float* __restrict__ node_h, const float* __restrict__ agg,
    const float* __restrict__ Wg, const float* __restrict__ bg,
    const float* __restrict__ lns, const float* __restrict__ lnb,
    const float* __restrict__ Wtop, float* __restrict__ ga, float* __restrict__ gc)
{
    constexpr int K = 2 * H;
    extern __shared__ float sm[];
    float4* Ws4 = (float4*)sm;                 // [256][32] float4
    float4* As4 = (float4*)(sm + K * H);       // [64][64] float4
    const int tid  = threadIdx.x;
    const int row0 = blockIdx.x * 64;

    const float4* Wg4 = (const float4*)Wg;
    #pragma unroll 4
    for (int i = tid; i < K * H / 4; i += 256) Ws4[i] = Wg4[i];

    for (int i = tid; i < 64 * (K / 4); i += 256) {
        int r = i / (K / 4), c = i % (K / 4);
        int row = row0 + r;
        float4 v = make_float4(0.f, 0.f, 0.f, 0.f);
        if (row < NN) {
            if (c < 32) v = ((const float4*)(node_h + (long)row * H))[c];
            else        v = ((const float4*)(agg    + (long)row * H))[c - 32];
        }
        As4[i] = v;
    }
    __syncthreads();

    const int lane = tid & 31, warp = tid >> 5;
    const int rb = warp * 8;
    float acc[8][4];
    #pragma unroll
    for (int r = 0; r < 8; r++) { acc[r][0]=0.f; acc[r][1]=0.f; acc[r][2]=0.f; acc[r][3]=0.f; }

    #pragma unroll 2
    for (int k = 0; k < K; k += 4) {
        float4 w0 = Ws4[(k + 0) * 32 + lane];
        float4 w1 = Ws4[(k + 1) * 32 + lane];
        float4 w2 = Ws4[(k + 2) * 32 + lane];
        float4 w3 = Ws4[(k + 3) * 32 + lane];
        #pragma unroll
        for (int r = 0; r < 8; r++) {
            float4 a = As4[(rb + r) * (K / 4) + (k >> 2)];
            acc[r][0] += a.x*w0.x + a.y*w1.x + a.z*w2.x + a.w*w3.x;
            acc[r][1] += a.x*w0.y + a.y*w1.y + a.z*w2.y + a.w*w3.y;
            acc[r][2] += a.x*w0.z + a.y*w1.z + a.z*w2.z + a.w*w3.z;
            acc[r][3] += a.x*w0.w + a.y*w1.w + a.z*w2.w + a.w*w3.w;
        }
    }

    float4 b4 = ((const float4*)bg)[lane];
    float4 s4 = ((const float4*)lns)[lane];
    float4 t4 = ((const float4*)lnb)[lane];
    float4 ts = ((const float4*)Wtop)[lane];
    float4 td = ((const float4*)Wtop)[32 + lane];

    #pragma unroll
    for (int r = 0; r < 8; r++) {
        int row = row0 + rb + r;
        if (row < NN) {                                    // warp-uniform
            float4 resid = As4[(rb + r) * (K / 4) + lane]; // node_h slice
            float x0 = resid.x + acc[r][0] + b4.x;
            float x1 = resid.y + acc[r][1] + b4.y;
            float x2 = resid.z + acc[r][2] + b4.z;
            float x3 = resid.w + acc[r][3] + b4.w;
            float sum = warp_sum(x0 + x1 + x2 + x3);
            float sq  = warp_sum(x0*x0 + x1*x1 + x2*x2 + x3*x3);
            float mean = sum * (1.f / H);
            float var  = sq  * (1.f / H) - mean * mean;
            float rstd = rsqrtf(var + 1e-6f);
            float y0 = fmaxf((x0 - mean) * rstd * s4.x + t4.x, 0.f);
            float y1 = fmaxf((x1 - mean) * rstd * s4.y + t4.y, 0.f);
            float y2 = fmaxf((x2 - mean) * rstd * s4.z + t4.z, 0.f);
            float y3 = fmaxf((x3 - mean) * rstd * s4.w + t4.w, 0.f);
            ((float4*)(node_h + (long)row * H))[lane] = make_float4(y0, y1, y2, y3);
            float pa = warp_sum(y0*ts.x + y1*ts.y + y2*ts.z + y3*ts.w);
            float pc = warp_sum(y0*td.x + y1*td.y + y2*td.z + y3*td.w);
            if (lane == 0) { ga[row] = pa; gc[row] = pc; }
        }
    }
}

// ---------------- launch ----------------
extern "C" void kernel_launch(void* const* d_in, const int* in_sizes, int n_in,
                              void* d_out, int out_size)
{
    const float* node_features = (const float*)d_in[0];
    const float* edge_features = (const float*)d_in[1];
    const int*   eidx          = (const int*)  d_in[2];
    const float* W_node = (const float*)d_in[3];
    const float* b_node = (const float*)d_in[4];
    const float* W_edge = (const float*)d_in[5];
    const float* b_edge = (const float*)d_in[6];
    const float* W_gnn  = (const float*)d_in[7];
    const float* b_gnn  = (const float*)d_in[8];
    const float* W_top  = (const float*)d_in[9];
    const float* b_top  = (const float*)d_in[10];
    const float* ln_s   = (const float*)d_in[11];
    const float* ln_b   = (const float*)d_in[12];

    float *node_h, *agge, *agg, *edot, *ga, *gc, *ew;
    cudaGetSymbolAddress((void**)&node_h, g_node_h);
    cudaGetSymbolAddress((void**)&agge,   g_agg_edge);
    cudaGetSymbolAddress((void**)&agg,    g_agg);
    cudaGetSymbolAddress((void**)&edot,   g_edot);
    cudaGetSymbolAddress((void**)&ga,     g_a);
    cudaGetSymbolAddress((void**)&gc,     g_c);
    cudaGetSymbolAddress((void**)&ew,     g_ew);

    cudaFuncSetAttribute(k_node_embed, cudaFuncAttributeMaxDynamicSharedMemorySize, 98304);
    cudaFuncSetAttribute(k_edge_embed, cudaFuncAttributeMaxDynamicSharedMemorySize, 49152);
    cudaFuncSetAttribute(k_gnn_update, cudaFuncAttributeMaxDynamicSharedMemorySize, 196608);

    cudaMemsetAsync(agge, 0, (size_t)NN * H * sizeof(float), 0);

    k_node_embed<<<(NN + 63) / 64, 256, 98304>>>(node_features, W_node, b_node, W_top,
                                                 node_h, ga, gc);
    k_edge_embed<<<NE / 64, 256, 49152>>>(edge_features, W_edge, b_edge, W_top, b_top,
                                          eidx, edot, agge);

    for (int i = 0; i < NL; i++) {
        cudaMemcpyAsync(agg, agge, (size_t)NN * H * sizeof(float), cudaMemcpyDeviceToDevice, 0);
        k_scatter<<<NE / 8, 256>>>(node_h, eidx, ga, gc, edot, ew, agg);
        k_gnn_update<<<(NN + 63) / 64, 256, 196608>>>(node_h, agg,
            W_gnn + (long)i * 2 * H * H, b_gnn + (long)i * H,
            ln_s + (long)i * H, ln_b + (long)i * H, W_top, ga, gc);
    }

    float* out = (float*)d_out;
    cudaMemcpyAsync(out, node_h, (size_t)NN * H * sizeof(float), cudaMemcpyDeviceToDevice, 0);
    cudaMemcpyAsync(out + (size_t)NN * H, ew, (size_t)NE * sizeof(float), cudaMemcpyDeviceToDevice, 0);
}

// round 4
// speedup vs baseline: 1.8544x; 1.8544x over previous
#include <cuda_runtime.h>
#include <cuda_bf16.h>
#include <stdint.h>
#include <math.h>

#define NN 50000
#define NE 200000
#define H  128
#define NL 3

// ---------------- scratch (device globals: allocation-free) ----------------
__device__ float g_node_h[NN * H];
__device__ float g_agg_edge[NN * H];
__device__ float g_agg[NN * H];
__device__ float g_edot[NE];
__device__ float g_a[NN];
__device__ float g_c[NN];
__device__ float g_ew[NE];
// bf16 hi/lo weight images, transposed to [n][k] row-major
__device__ __align__(16) __nv_bfloat16 g_Bn_hi[128 * 128];
__device__ __align__(16) __nv_bfloat16 g_Bn_lo[128 * 128];
__device__ __align__(16) __nv_bfloat16 g_Be_hi[128 * 64];
__device__ __align__(16) __nv_bfloat16 g_Be_lo[128 * 64];
__device__ __align__(16) __nv_bfloat16 g_Bg_hi[NL][128 * 256];
__device__ __align__(16) __nv_bfloat16 g_Bg_lo[NL][128 * 256];

// ---------------- helpers ----------------
__device__ __forceinline__ uint32_t smem_u32(const void* p) {
    uint32_t a;
    asm("{ .reg .u64 t; cvta.to.shared.u64 t, %1; cvt.u32.u64 %0, t; }" : "=r"(a) : "l"(p));
    return a;
}
__device__ __forceinline__ float quad2(float v) {
    v += __shfl_xor_sync(0xffffffffu, v, 1);
    v += __shfl_xor_sync(0xffffffffu, v, 2);
    return v;
}
__device__ __forceinline__ void red_add_v4(float* addr, float4 v) {
    asm volatile("red.global.add.v4.f32 [%0], {%1,%2,%3,%4};"
                 :: "l"(addr), "f"(v.x), "f"(v.y), "f"(v.z), "f"(v.w) : "memory");
}
// fp32 pair -> packed bf16 hi (x) and lo (y)
__device__ __forceinline__ uint2 split2(float2 v) {
    __nv_bfloat162 h = __floats2bfloat162_rn(v.x, v.y);
    float2 f = __bfloat1622float2(h);
    __nv_bfloat162 l = __floats2bfloat162_rn(v.x - f.x, v.y - f.y);
    return make_uint2(*(uint32_t*)&h, *(uint32_t*)&l);
}
__device__ __forceinline__ void ldsm4(uint32_t& r0, uint32_t& r1, uint32_t& r2, uint32_t& r3,
                                      uint32_t addr) {
    asm volatile("ldmatrix.sync.aligned.m8n8.x4.shared.b16 {%0,%1,%2,%3}, [%4];"
                 : "=r"(r0), "=r"(r1), "=r"(r2), "=r"(r3) : "r"(addr));
}
__device__ __forceinline__ void mma16816(float* d, const uint32_t* a, uint32_t b0, uint32_t b1) {
    asm volatile(
        "mma.sync.aligned.m16n8k16.row.col.f32.bf16.bf16.f32 "
        "{%0,%1,%2,%3}, {%4,%5,%6,%7}, {%8,%9}, {%0,%1,%2,%3};"
        : "+f"(d[0]), "+f"(d[1]), "+f"(d[2]), "+f"(d[3])
        : "r"(a[0]), "r"(a[1]), "r"(a[2]), "r"(a[3]), "r"(b0), "r"(b1));
}

// Mainloop over NKS k16-steps: A direct from global (rows Ar0/Ar8) with in-reg
// bf16 hi/lo split; B fragments from smem via ldmatrix.x4; 3-product accumulate.
template<int NKS, int KPAD>
__device__ __forceinline__ void mma_mainloop(float (*d)[4], const float* __restrict__ Ar0,
                                             const float* __restrict__ Ar8,
                                             uint32_t sBh, uint32_t sBl, int lane) {
    const int q2 = (lane & 3) * 2;
    const int nb = ((lane >> 4) << 3) + (lane & 7);
    const int kb = ((lane >> 3) & 1) << 3;
    #pragma unroll 2
    for (int ks = 0; ks < NKS; ks++) {
        int k0 = ks * 16 + q2;
        uint32_t ahi[4], alo[4];
        uint2 s;
        s = split2(*(const float2*)(Ar0 + k0));     ahi[0] = s.x; alo[0] = s.y;
        s = split2(*(const float2*)(Ar8 + k0));     ahi[1] = s.x; alo[1] = s.y;
        s = split2(*(const float2*)(Ar0 + k0 + 8)); ahi[2] = s.x; alo[2] = s.y;
        s = split2(*(const float2*)(Ar8 + k0 + 8)); ahi[3] = s.x; alo[3] = s.y;
        #pragma unroll
        for (int p = 0; p < 8; p++) {
            uint32_t off = (uint32_t)(((p * 16 + nb) * KPAD + ks * 16 + kb) * 2);
            uint32_t bh0, bh1, bh2, bh3, bl0, bl1, bl2, bl3;
            ldsm4(bh0, bh1, bh2, bh3, sBh + off);
            ldsm4(bl0, bl1, bl2, bl3, sBl + off);
            mma16816(d[2 * p],     ahi, bh0, bh1);
            mma16816(d[2 * p],     ahi, bl0, bl1);
            mma16816(d[2 * p],     alo, bh0, bh1);
            mma16816(d[2 * p + 1], ahi, bh2, bh3);
            mma16816(d[2 * p + 1], ahi, bl2, bl3);
            mma16816(d[2 * p + 1], alo, bh2, bh3);
        }
    }
}

// ---------------- weight prep: fp32 W[k][n] -> bf16 hi/lo [n][k] -----------
__global__ void k_prep(const float* __restrict__ Wn, const float* __restrict__ We,
                       const float* __restrict__ Wg) {
    int stride = gridDim.x * blockDim.x;
    int t0 = blockIdx.x * blockDim.x + threadIdx.x;
    for (int i = t0; i < 128 * 128; i += stride) {
        int k = i >> 7, n = i & 127;
        float w = Wn[i];
        __nv_bfloat16 hi = __float2bfloat16(w);
        g_Bn_hi[n * 128 + k] = hi;
        g_Bn_lo[n * 128 + k] = __float2bfloat16(w - __bfloat162float(hi));
    }
    for (int i = t0; i < 64 * 128; i += stride) {
        int k = i >> 7, n = i & 127;
        float w = We[i];
        __nv_bfloat16 hi = __float2bfloat16(w);
        g_Be_hi[n * 64 + k] = hi;
        g_Be_lo[n * 64 + k] = __float2bfloat16(w - __bfloat162float(hi));
    }
    for (int i = t0; i < NL * 256 * 128; i += stride) {
        int l = i / (256 * 128);
        int j = i - l * 256 * 128;
        int k = j >> 7, n = j & 127;
        float w = Wg[i];
        __nv_bfloat16 hi = __float2bfloat16(w);
        g_Bg_hi[l][n * 256 + k] = hi;
        g_Bg_lo[l][n * 256 + k] = __float2bfloat16(w - __bfloat162float(hi));
    }
}

// ---------------- node embed: node_h = A @ Wn + bn; ga/gc dots -------------
__global__ __launch_bounds__(256, 2) void k_mma_node(
    const float* __restrict__ A, const __nv_bfloat16* __restrict__ Bhi,
    const __nv_bfloat16* __restrict__ Blo, const float* __restrict__ bn,
    const float* __restrict__ Wtop, float* __restrict__ node_h,
    float* __restrict__ ga, float* __restrict__ gc) {
    extern __shared__ char sm[];
    const int KPAD = 136, BSPLIT = 128 * KPAD * 2;   // bytes per split
    int tid = threadIdx.x, w = tid >> 5, lane = tid & 31;
    int q = lane & 3, g = lane >> 2;
    long row0 = (long)blockIdx.x * 128;

    const uint4* sh = (const uint4*)Bhi;
    const uint4* sl = (const uint4*)Blo;
    for (int i = tid; i < 128 * 16; i += 256) {
        int r = i >> 4, c = i & 15;
        *(uint4*)(sm + r * 272 + c * 16) = sh[r * 16 + c];
        *(uint4*)(sm + BSPLIT + r * 272 + c * 16) = sl[r * 16 + c];
    }
    __syncthreads();

    long rg = row0 + w * 16 + g, rg8 = rg + 8;
    long rgl = rg < NN ? rg : NN - 1, rg8l = rg8 < NN ? rg8 : NN - 1;
    float d[16][4];
    #pragma unroll
    for (int i = 0; i < 16; i++) { d[i][0] = d[i][1] = d[i][2] = d[i][3] = 0.f; }
    mma_mainloop<8, 136>(d, A + rgl * 128, A + rg8l * 128,
                         smem_u32(sm), smem_u32(sm) + BSPLIT, lane);

    float pa0 = 0.f, pc0 = 0.f, pa8 = 0.f, pc8 = 0.f;
    #pragma unroll
    for (int nf = 0; nf < 16; nf++) {
        int cn = nf * 8 + q * 2;
        float2 b  = *(const float2*)(bn + cn);
        float2 ts = *(const float2*)(Wtop + cn);
        float2 td = *(const float2*)(Wtop + 128 + cn);
        float y00 = d[nf][0] + b.x, y01 = d[nf][1] + b.y;
        float y80 = d[nf][2] + b.x, y81 = d[nf][3] + b.y;
        if (rg  < NN) *(float2*)(node_h + rg  * 128 + cn) = make_float2(y00, y01);
        if (rg8 < NN) *(float2*)(node_h + rg8 * 128 + cn) = make_float2(y80, y81);
        pa0 += y00 * ts.x + y01 * ts.y; pc0 += y00 * td.x + y01 * td.y;
        pa8 += y80 * ts.x + y81 * ts.y; pc8 += y80 * td.x + y81 * td.y;
    }
    pa0 = quad2(pa0); pc0 = quad2(pc0); pa8 = quad2(pa8); pc8 = quad2(pc8);
    if (q == 0) {
        if (rg  < NN) { ga[rg]  = pa0; gc[rg]  = pc0; }
        if (rg8 < NN) { ga[rg8] = pa8; gc[rg8] = pc8; }
    }
}

// ---------------- edge embed (fused): edot + agge scatter ------------------
__global__ __launch_bounds__(256, 2) void k_mma_edge(
    const float* __restrict__ A, const __nv_bfloat16* __restrict__ Bhi,
    const __nv_bfloat16* __restrict__ Blo, const float* __restrict__ be,
    const float* __restrict__ Wtop, const float* __restrict__ btop,
    const int* __restrict__ eidx, float* __restrict__ edot, float* __restrict__ agge) {
    extern __shared__ char sm[];
    const int KPAD = 72, BSPLIT = 128 * KPAD * 2;         // 18432 B per split
    const int OFF_STAGE = 2 * BSPLIT;                     // 36864, 16B aligned
    float* stage = (float*)(sm + OFF_STAGE);              // [128][132]
    int tid = threadIdx.x, w = tid >> 5, lane = tid & 31;
    int q = lane & 3, g = lane >> 2;
    long row0 = (long)blockIdx.x * 128;

    const uint4* sh = (const uint4*)Bhi;
    const uint4* sl = (const uint4*)Blo;
    for (int i = tid; i < 128 * 8; i += 256) {
        int r = i >> 3, c = i & 7;
        *(uint4*)(sm + r * 144 + c * 16) = sh[r * 8 + c];
        *(uint4*)(sm + BSPLIT + r * 144 + c * 16) = sl[r * 8 + c];
    }
    __syncthreads();

    long rg = row0 + w * 16 + g, rg8 = rg + 8;
    long rgl = rg < NE ? rg : NE - 1, rg8l = rg8 < NE ? rg8 : NE - 1;
    float d[16][4];
    #pragma unroll
    for (int i = 0; i < 16; i++) { d[i][0] = d[i][1] = d[i][2] = d[i][3] = 0.f; }
    mma_mainloop<4, 72>(d, A + rgl * 64, A + rg8l * 64,
                        smem_u32(sm), smem_u32(sm) + BSPLIT, lane);

    int r0 = w * 16 + g, r8 = r0 + 8;
    float pe0 = 0.f, pe8 = 0.f;
    #pragma unroll
    for (int nf = 0; nf < 16; nf++) {
        int cn = nf * 8 + q * 2;
        float2 b  = *(const float2*)(be + cn);
        float2 te = *(const float2*)(Wtop + 256 + cn);
        float y00 = d[nf][0] + b.x, y01 = d[nf][1] + b.y;
        float y80 = d[nf][2] + b.x, y81 = d[nf][3] + b.y;
        *(float2*)(stage + r0 * 132 + cn) = make_float2(y00, y01);
        *(float2*)(stage + r8 * 132 + cn) = make_float2(y80, y81);
        pe0 += y00 * te.x + y01 * te.y;
        pe8 += y80 * te.x + y81 * te.y;
    }
    pe0 = quad2(pe0); pe8 = quad2(pe8);
    float bt = btop[0];
    if (q == 0) {
        if (rg  < NE) edot[rg]  = pe0 + bt;
        if (rg8 < NE) edot[rg8] = pe8 + bt;
    }
    __syncthreads();
    // warp-per-row scatter of edge_h into agge[dst]
    #pragma unroll 4
    for (int rr = 0; rr < 16; rr++) {
        int r_local = rr * 8 + w;
        long e = row0 + r_local;
        if (e < NE) {
            int dst = eidx[NE + e];
            float4 v = *(float4*)(stage + r_local * 132 + lane * 4);
            red_add_v4(agge + (long)dst * H + lane * 4, v);
        }
    }
}

// ---------------- per layer: edge weight + scatter w*node_h[src] -----------
__global__ __launch_bounds__(256) void k_scatter(
    const float* __restrict__ node_h, const int* __restrict__ eidx,
    const float* __restrict__ ga, const float* __restrict__ gc,
    const float* __restrict__ edot, float* __restrict__ ew, float* __restrict__ agg) {
    int e = blockIdx.x * 8 + (threadIdx.x >> 5);
    int lane = threadIdx.x & 31;
    if (e >= NE) return;
    int s = eidx[e], d = eidx[NE + e];
    float x = ga[s] + gc[d] + edot[e];
    float w = 1.f / (1.f + expf(-x));
    if (lane == 0) ew[e] = w;
    float4 h = ((const float4*)(node_h + (long)s * H))[lane];
    red_add_v4(agg + (long)d * H + lane * 4, make_float4(w * h.x, w * h.y, w * h.z, w * h.w));
}

// ------- node update: GEMM K=256 + bias + residual + LN + ReLU + dots ------
__global__ __launch_bounds__(256, 2) void k_mma_update(
    float* __restrict__ node_h, const float* __restrict__ agg,
    const __nv_bfloat16* __restrict__ Bhi, const __nv_bfloat16* __restrict__ Blo,
    const float* __restrict__ bg, const float* __restrict__ lns,
    const float* __restrict__ lnb, const float* __restrict__ Wtop,
    float* __restrict__ ga, float* __restrict__ gc) {
    extern __shared__ char sm[];
    const int KPAD = 136, BSPLIT = 128 * KPAD * 2;
    int tid = threadIdx.x, w = tid >> 5, lane = tid & 31;
    int q = lane & 3, g = lane >> 2;
    long row0 = (long)blockIdx.x * 128;

    long rg = row0 + w * 16 + g, rg8 = rg + 8;
    long rgl = rg < NN ? rg : NN - 1, rg8l = rg8 < NN ? rg8 : NN - 1;
    float d[16][4];
    #pragma unroll
    for (int i = 0; i < 16; i++) { d[i][0] = d[i][1] = d[i][2] = d[i][3] = 0.f; }

    const uint4* sh = (const uint4*)Bhi;
    const uint4* sl = (const uint4*)Blo;
    #pragma unroll 1
    for (int ch = 0; ch < 2; ch++) {
        for (int i = tid; i < 128 * 16; i += 256) {
            int r = i >> 4, c = i & 15;
            *(uint4*)(sm + r * 272 + c * 16) = sh[r * 32 + ch * 16 + c];
            *(uint4*)(sm + BSPLIT + r * 272 + c * 16) = sl[r * 32 + ch * 16 + c];
        }
        __syncthreads();
        const float* Asrc = ch ? agg : node_h;
        mma_mainloop<8, 136>(d, Asrc + rgl * 128, Asrc + rg8l * 128,
                             smem_u32(sm), smem_u32(sm) + BSPLIT, lane);
        __syncthreads();
    }

    // epilogue: bias + residual -> LN stats (quad reduce) -> LN+ReLU + dots
    float s0 = 0.f, sq0 = 0.f, s8 = 0.f, sq8 = 0.f;
    #pragma unroll
    for (int nf = 0; nf < 16; nf++) {
        int cn = nf * 8 + q * 2;
        float2 b  = *(const float2*)(bg + cn);
        float2 r0v = *(const float2*)(node_h + rgl * 128 + cn);
        float2 r8v = *(const float2*)(node_h + rg8l * 128 + cn);
        float x00 = d[nf][0] + b.x + r0v.x, x01 = d[nf][1] + b.y + r0v.y;
        float x80 = d[nf][2] + b.x + r8v.x, x81 = d[nf][3] + b.y + r8v.y;
        d[nf][0] = x00; d[nf][1] = x01; d[nf][2] = x80; d[nf][3] = x81;
        s0 += x00 + x01; sq0 += x00 * x00 + x01 * x01;
        s8 += x80 + x81; sq8 += x80 * x80 + x81 * x81;
    }
    s0 = quad2(s0); sq0 = quad2(sq0); s8 = quad2(s8); sq8 = quad2(sq8);
    float m0 = s0 * (1.f / H), m8 = s8 * (1.f / H);
    float rstd0 = rsqrtf(sq0 * (1.f / H) - m0 * m0 + 1e-6f);
    float rstd8 = rsqrtf(sq8 * (1.f / H) - m8 * m8 + 1e-6f);

    float pa0 = 0.f, pc0 = 0.f, pa8 = 0.f, pc8 = 0.f;
    #pragma unroll
    for (int nf = 0; nf < 16; nf++) {
        int cn = nf * 8 + q * 2;
        float2 sc = *(const float2*)(lns + cn);
        float2 bi = *(const float2*)(lnb + cn);
        float2 ts = *(const float2*)(Wtop + cn);
        float2 td = *(const float2*)(Wtop + 128 + cn);
        float y00 = fmaxf((d[nf][0] - m0) * rstd0 * sc.x + bi.x, 0.f);
        float y01 = fmaxf((d[nf][1] - m0) * rstd0 * sc.y + bi.y, 0.f);
        float y80 = fmaxf((d[nf][2] - m8) * rstd8 * sc.x + bi.x, 0.f);
        float y81 = fmaxf((d[nf][3] - m8) * rstd8 * sc.y + bi.y, 0.f);
        if (rg  < NN) *(float2*)(node_h + rg  * 128 + cn) = make_float2(y00, y01);
        if (rg8 < NN) *(float2*)(node_h + rg8 * 128 + cn) = make_float2(y80, y81);
        pa0 += y00 * ts.x + y01 * ts.y; pc0 += y00 * td.x + y01 * td.y;
        pa8 += y80 * ts.x + y81 * ts.y; pc8 += y80 * td.x + y81 * td.y;
    }
    pa0 = quad2(pa0); pc0 = quad2(pc0); pa8 = quad2(pa8); pc8 = quad2(pc8);
    if (q == 0) {
        if (rg  < NN) { ga[rg]  = pa0; gc[rg]  = pc0; }
        if (rg8 < NN) { ga[rg8] = pa8; gc[rg8] = pc8; }
    }
}

// ---------------- launch ----------------
extern "C" void kernel_launch(void* const* d_in, const int* in_sizes, int n_in,
                              void* d_out, int out_size) {
    const float* node_features = (const float*)d_in[0];
    const float* edge_features = (const float*)d_in[1];
    const int*   eidx          = (const int*)d_in[2];
    const float* W_node = (const float*)d_in[3];
    const float* b_node = (const float*)d_in[4];
    const float* W_edge = (const float*)d_in[5];
    const float* b_edge = (const float*)d_in[6];
    const float* W_gnn  = (const float*)d_in[7];
    const float* b_gnn  = (const float*)d_in[8];
    const float* W_top  = (const float*)d_in[9];
    const float* b_top  = (const float*)d_in[10];
    const float* ln_s   = (const float*)d_in[11];
    const float* ln_b   = (const float*)d_in[12];

    float *node_h, *agge, *agg, *edot, *ga, *gc, *ew;
    cudaGetSymbolAddress((void**)&node_h, g_node_h);
    cudaGetSymbolAddress((void**)&agge, g_agg_edge);
    cudaGetSymbolAddress((void**)&agg, g_agg);
    cudaGetSymbolAddress((void**)&edot, g_edot);
    cudaGetSymbolAddress((void**)&ga, g_a);
    cudaGetSymbolAddress((void**)&gc, g_c);
    cudaGetSymbolAddress((void**)&ew, g_ew);
    __nv_bfloat16 *Bn_hi, *Bn_lo, *Be_hi, *Be_lo, *Bg_hi, *Bg_lo;
    cudaGetSymbolAddress((void**)&Bn_hi, g_Bn_hi);
    cudaGetSymbolAddress((void**)&Bn_lo, g_Bn_lo);
    cudaGetSymbolAddress((void**)&Be_hi, g_Be_hi);
    cudaGetSymbolAddress((void**)&Be_lo, g_Be_lo);
    cudaGetSymbolAddress((void**)&Bg_hi, g_Bg_hi);
    cudaGetSymbolAddress((void**)&Bg_lo, g_Bg_lo);

    const int SM_NODE = 128 * 136 * 2 * 2;                     // 69632
    const int SM_EDGE = 128 * 72 * 2 * 2 + 128 * 132 * 4;      // 104448
    const int SM_UPD  = 128 * 136 * 2 * 2;                     // 69632
    cudaFuncSetAttribute(k_mma_node, cudaFuncAttributeMaxDynamicSharedMemorySize, SM_NODE);
    cudaFuncSetAttribute(k_mma_edge, cudaFuncAttributeMaxDynamicSharedMemorySize, SM_EDGE);
    cudaFuncSetAttribute(k_mma_update, cudaFuncAttributeMaxDynamicSharedMemorySize, SM_UPD);

    cudaMemsetAsync(agge, 0, (size_t)NN * H * sizeof(float), 0);
    k_prep<<<64, 256>>>(W_node, W_edge, W_gnn);

    k_mma_node<<<(NN + 127) / 128, 256, SM_NODE>>>(node_features, Bn_hi, Bn_lo, b_node, W_top,
                                                   node_h, ga, gc);
    k_mma_edge<<<(NE + 127) / 128, 256, SM_EDGE>>>(edge_features, Be_hi, Be_lo, b_edge, W_top,
                                                   b_top, eidx, edot, agge);

    for (int i = 0; i < NL; i++) {
        cudaMemcpyAsync(agg, agge, (size_t)NN * H * sizeof(float), cudaMemcpyDeviceToDevice, 0);
        k_scatter<<<NE / 8, 256>>>(node_h, eidx, ga, gc, edot, ew, agg);
        k_mma_update<<<(NN + 127) / 128, 256, SM_UPD>>>(node_h, agg,
            Bg_hi + (size_t)i * 128 * 256, Bg_lo + (size_t)i * 128 * 256,
            b_gnn + (size_t)i * H, ln_s + (size_t)i * H, ln_b + (size_t)i * H, W_top, ga, gc);
    }

    float* out = (float*)d_out;
    cudaMemcpyAsync(out, node_h, (size_t)NN * H * sizeof(float), cudaMemcpyDeviceToDevice, 0);
    cudaMemcpyAsync(out + (size_t)NN * H, ew, (size_t)NE * sizeof(float),
                    cudaMemcpyDeviceToDevice, 0);
}

// round 6
// speedup vs baseline: 2.0475x; 1.1042x over previous
#include <cuda_runtime.h>
#include <cuda_bf16.h>
#include <stdint.h>
#include <math.h>

#define NN 50000
#define NE 200000
#define H  128
#define NL 3
#define NB_SCAN ((NN + 255) / 256)

// ---------------- scratch (device globals: allocation-free) ----------------
__device__ float g_node_h[NN * H];
__device__ float g_agg_edge[NN * H];
__device__ float g_agg[NN * H];
__device__ float g_edot[NE];
__device__ float g_a[NN];
__device__ float g_c[NN];
// CSR by dst
__device__ int g_cnt[NN];
__device__ int g_off[NN + 1];
__device__ int g_cur[NN];
__device__ int g_se[NE];
__device__ int g_ss[NE];
__device__ int g_bsum[NB_SCAN];
__device__ int g_bpre[NB_SCAN];
// bf16 hi/lo weight images, transposed to [n][k] row-major
__device__ __align__(16) __nv_bfloat16 g_Bn_hi[128 * 128];
__device__ __align__(16) __nv_bfloat16 g_Bn_lo[128 * 128];
__device__ __align__(16) __nv_bfloat16 g_Be_hi[128 * 64];
__device__ __align__(16) __nv_bfloat16 g_Be_lo[128 * 64];
__device__ __align__(16) __nv_bfloat16 g_Bg_hi[NL][128 * 256];
__device__ __align__(16) __nv_bfloat16 g_Bg_lo[NL][128 * 256];

// ---------------- helpers ----------------
__device__ __forceinline__ uint32_t smem_u32(const void* p) {
    uint32_t a;
    asm("{ .reg .u64 t; cvta.to.shared.u64 t, %1; cvt.u32.u64 %0, t; }" : "=r"(a) : "l"(p));
    return a;
}
__device__ __forceinline__ float quad2(float v) {
    v += __shfl_xor_sync(0xffffffffu, v, 1);
    v += __shfl_xor_sync(0xffffffffu, v, 2);
    return v;
}
__device__ __forceinline__ void red_add_v4(float* addr, float4 v) {
    asm volatile("red.global.add.v4.f32 [%0], {%1,%2,%3,%4};"
                 :: "l"(addr), "f"(v.x), "f"(v.y), "f"(v.z), "f"(v.w) : "memory");
}
__device__ __forceinline__ uint2 split2(float2 v) {
    __nv_bfloat162 h = __floats2bfloat162_rn(v.x, v.y);
    float2 f = __bfloat1622float2(h);
    __nv_bfloat162 l = __floats2bfloat162_rn(v.x - f.x, v.y - f.y);
    return make_uint2(*(uint32_t*)&h, *(uint32_t*)&l);
}
__device__ __forceinline__ void ldsm4(uint32_t& r0, uint32_t& r1, uint32_t& r2, uint32_t& r3,
                                      uint32_t addr) {
    asm volatile("ldmatrix.sync.aligned.m8n8.x4.shared.b16 {%0,%1,%2,%3}, [%4];"
                 : "=r"(r0), "=r"(r1), "=r"(r2), "=r"(r3) : "r"(addr));
}
__device__ __forceinline__ void mma16816(float* d, const uint32_t* a, uint32_t b0, uint32_t b1) {
    asm volatile(
        "mma.sync.aligned.m16n8k16.row.col.f32.bf16.bf16.f32 "
        "{%0,%1,%2,%3}, {%4,%5,%6,%7}, {%8,%9}, {%0,%1,%2,%3};"
        : "+f"(d[0]), "+f"(d[1]), "+f"(d[2]), "+f"(d[3])
        : "r"(a[0]), "r"(a[1]), "r"(a[2]), "r"(a[3]), "r"(b0), "r"(b1));
}

template<int NKS, int KPAD>
__device__ __forceinline__ void mma_mainloop(float (*d)[4], const float* __restrict__ Ar0,
                                             const float* __restrict__ Ar8,
                                             uint32_t sBh, uint32_t sBl, int lane) {
    const int q2 = (lane & 3) * 2;
    const int nb = ((lane >> 4) << 3) + (lane & 7);
    const int kb = ((lane >> 3) & 1) << 3;
    #pragma unroll 2
    for (int ks = 0; ks < NKS; ks++) {
        int k0 = ks * 16 + q2;
        uint32_t ahi[4], alo[4];
        uint2 s;
        s = split2(*(const float2*)(Ar0 + k0));     ahi[0] = s.x; alo[0] = s.y;
        s = split2(*(const float2*)(Ar8 + k0));     ahi[1] = s.x; alo[1] = s.y;
        s = split2(*(const float2*)(Ar0 + k0 + 8)); ahi[2] = s.x; alo[2] = s.y;
        s = split2(*(const float2*)(Ar8 + k0 + 8)); ahi[3] = s.x; alo[3] = s.y;
        #pragma unroll
        for (int p = 0; p < 8; p++) {
            uint32_t off = (uint32_t)(((p * 16 + nb) * KPAD + ks * 16 + kb) * 2);
            uint32_t bh0, bh1, bh2, bh3, bl0, bl1, bl2, bl3;
            ldsm4(bh0, bh1, bh2, bh3, sBh + off);
            ldsm4(bl0, bl1, bl2, bl3, sBl + off);
            mma16816(d[2 * p],     ahi, bh0, bh1);
            mma16816(d[2 * p],     ahi, bl0, bl1);
            mma16816(d[2 * p],     alo, bh0, bh1);
            mma16816(d[2 * p + 1], ahi, bh2, bh3);
            mma16816(d[2 * p + 1], ahi, bl2, bl3);
            mma16816(d[2 * p + 1], alo, bh2, bh3);
        }
    }
}

// ---------------- weight prep ----------------
__global__ void k_prep(const float* __restrict__ Wn, const float* __restrict__ We,
                       const float* __restrict__ Wg) {
    int stride = gridDim.x * blockDim.x;
    int t0 = blockIdx.x * blockDim.x + threadIdx.x;
    for (int i = t0; i < 128 * 128; i += stride) {
        int k = i >> 7, n = i & 127;
        float w = Wn[i];
        __nv_bfloat16 hi = __float2bfloat16(w);
        g_Bn_hi[n * 128 + k] = hi;
        g_Bn_lo[n * 128 + k] = __float2bfloat16(w - __bfloat162float(hi));
    }
    for (int i = t0; i < 64 * 128; i += stride) {
        int k = i >> 7, n = i & 127;
        float w = We[i];
        __nv_bfloat16 hi = __float2bfloat16(w);
        g_Be_hi[n * 64 + k] = hi;
        g_Be_lo[n * 64 + k] = __float2bfloat16(w - __bfloat162float(hi));
    }
    for (int i = t0; i < NL * 256 * 128; i += stride) {
        int l = i / (256 * 128);
        int j = i - l * 256 * 128;
        int k = j >> 7, n = j & 127;
        float w = Wg[i];
        __nv_bfloat16 hi = __float2bfloat16(w);
        g_Bg_hi[l][n * 256 + k] = hi;
        g_Bg_lo[l][n * 256 + k] = __float2bfloat16(w - __bfloat162float(hi));
    }
}

// ---------------- CSR build ----------------
__global__ void k_hist(const int* __restrict__ eidx) {
    int e = blockIdx.x * blockDim.x + threadIdx.x;
    if (e < NE) atomicAdd(&g_cnt[eidx[NE + e]], 1);
}
__global__ void k_scanA() {   // per-block sums of g_cnt
    __shared__ int s[256];
    int i = blockIdx.x * 256 + threadIdx.x;
    int v = (i < NN) ? g_cnt[i] : 0;
    s[threadIdx.x] = v;
    __syncthreads();
    for (int o = 128; o > 0; o >>= 1) {
        if (threadIdx.x < o) s[threadIdx.x] += s[threadIdx.x + o];
        __syncthreads();
    }
    if (threadIdx.x == 0) g_bsum[blockIdx.x] = s[0];
}
__global__ void k_scanB() {   // exclusive scan of block sums (single block)
    if (threadIdx.x == 0) {
        int acc = 0;
        for (int b = 0; b < NB_SCAN; b++) { int t = g_bsum[b]; g_bpre[b] = acc; acc += t; }
    }
}
__global__ void k_scanC() {   // per-element exclusive scan + base
    __shared__ int s[256];
    int i = blockIdx.x * 256 + threadIdx.x;
    int v = (i < NN) ? g_cnt[i] : 0;
    s[threadIdx.x] = v;
    __syncthreads();
    // Hillis-Steele inclusive scan
    for (int o = 1; o < 256; o <<= 1) {
        int t = (threadIdx.x >= o) ? s[threadIdx.x - o] : 0;
        __syncthreads();
        s[threadIdx.x] += t;
        __syncthreads();
    }
    if (i < NN) {
        int excl = g_bpre[blockIdx.x] + s[threadIdx.x] - v;
        g_off[i] = excl;
        g_cur[i] = excl;
        if (i == NN - 1) g_off[NN] = excl + v;
    }
}
__global__ void k_perm(const int* __restrict__ eidx) {
    int e = blockIdx.x * blockDim.x + threadIdx.x;
    if (e < NE) {
        int d = eidx[NE + e];
        int pos = atomicAdd(&g_cur[d], 1);
        g_se[pos] = e;
        g_ss[pos] = eidx[e];
    }
}

// ---------------- node embed ----------------
__global__ __launch_bounds__(256, 2) void k_mma_node(
    const float* __restrict__ A, const __nv_bfloat16* __restrict__ Bhi,
    const __nv_bfloat16* __restrict__ Blo, const float* __restrict__ bn,
    const float* __restrict__ Wtop, float* __restrict__ node_h,
    float* __restrict__ ga, float* __restrict__ gc) {
    extern __shared__ char sm[];
    const int KPAD = 136, BSPLIT = 128 * KPAD * 2;
    int tid = threadIdx.x, w = tid >> 5, lane = tid & 31;
    int q = lane & 3, g = lane >> 2;
    long row0 = (long)blockIdx.x * 128;

    const uint4* sh = (const uint4*)Bhi;
    const uint4* sl = (const uint4*)Blo;
    for (int i = tid; i < 128 * 16; i += 256) {
        int r = i >> 4, c = i & 15;
        *(uint4*)(sm + r * 272 + c * 16) = sh[r * 16 + c];
        *(uint4*)(sm + BSPLIT + r * 272 + c * 16) = sl[r * 16 + c];
    }
    __syncthreads();

    long rg = row0 + w * 16 + g, rg8 = rg + 8;
    long rgl = rg < NN ? rg : NN - 1, rg8l = rg8 < NN ? rg8 : NN - 1;
    float d[16][4];
    #pragma unroll
    for (int i = 0; i < 16; i++) { d[i][0] = d[i][1] = d[i][2] = d[i][3] = 0.f; }
    mma_mainloop<8, 136>(d, A + rgl * 128, A + rg8l * 128,
                         smem_u32(sm), smem_u32(sm) + BSPLIT, lane);

    float pa0 = 0.f, pc0 = 0.f, pa8 = 0.f, pc8 = 0.f;
    #pragma unroll
    for (int nf = 0; nf < 16; nf++) {
        int cn = nf * 8 + q * 2;
        float2 b  = *(const float2*)(bn + cn);
        float2 ts = *(const float2*)(Wtop + cn);
        float2 td = *(const float2*)(Wtop + 128 + cn);
        float y00 = d[nf][0] + b.x, y01 = d[nf][1] + b.y;
        float y80 = d[nf][2] + b.x, y81 = d[nf][3] + b.y;
        if (rg  < NN) *(float2*)(node_h + rg  * 128 + cn) = make_float2(y00, y01);
        if (rg8 < NN) *(float2*)(node_h + rg8 * 128 + cn) = make_float2(y80, y81);
        pa0 += y00 * ts.x + y01 * ts.y; pc0 += y00 * td.x + y01 * td.y;
        pa8 += y80 * ts.x + y81 * ts.y; pc8 += y80 * td.x + y81 * td.y;
    }
    pa0 = quad2(pa0); pc0 = quad2(pc0); pa8 = quad2(pa8); pc8 = quad2(pc8);
    if (q == 0) {
        if (rg  < NN) { ga[rg]  = pa0; gc[rg]  = pc0; }
        if (rg8 < NN) { ga[rg8] = pa8; gc[rg8] = pc8; }
    }
}

// ---------------- edge embed (fused): edot + agge scatter ------------------
__global__ __launch_bounds__(256, 2) void k_mma_edge(
    const float* __restrict__ A, const __nv_bfloat16* __restrict__ Bhi,
    const __nv_bfloat16* __restrict__ Blo, const float* __restrict__ be,
    const float* __restrict__ Wtop, const float* __restrict__ btop,
    const int* __restrict__ eidx, float* __restrict__ edot, float* __restrict__ agge) {
    extern __shared__ char sm[];
    const int KPAD = 72, BSPLIT = 128 * KPAD * 2;
    const int OFF_STAGE = 2 * BSPLIT;
    float* stage = (float*)(sm + OFF_STAGE);   // [128][132]
    int tid = threadIdx.x, w = tid >> 5, lane = tid & 31;
    int q = lane & 3, g = lane >> 2;
    long row0 = (long)blockIdx.x * 128;

    const uint4* sh = (const uint4*)Bhi;
    const uint4* sl = (const uint4*)Blo;
    for (int i = tid; i < 128 * 8; i += 256) {
        int r = i >> 3, c = i & 7;
        *(uint4*)(sm + r * 144 + c * 16) = sh[r * 8 + c];
        *(uint4*)(sm + BSPLIT + r * 144 + c * 16) = sl[r * 8 + c];
    }
    __syncthreads();

    long rg = row0 + w * 16 + g, rg8 = rg + 8;
    long rgl = rg < NE ? rg : NE - 1, rg8l = rg8 < NE ? rg8 : NE - 1;
    float d[16][4];
    #pragma unroll
    for (int i = 0; i < 16; i++) { d[i][0] = d[i][1] = d[i][2] = d[i][3] = 0.f; }
    mma_mainloop<4, 72>(d, A + rgl * 64, A + rg8l * 64,
                        smem_u32(sm), smem_u32(sm) + BSPLIT, lane);

    int r0 = w * 16 + g, r8 = r0 + 8;
    float pe0 = 0.f, pe8 = 0.f;
    #pragma unroll
    for (int nf = 0; nf < 16; nf++) {
        int cn = nf * 8 + q * 2;
        float2 b  = *(const float2*)(be + cn);
        float2 te = *(const float2*)(Wtop + 256 + cn);
        float y00 = d[nf][0] + b.x, y01 = d[nf][1] + b.y;
        float y80 = d[nf][2] + b.x, y81 = d[nf][3] + b.y;
        *(float2*)(stage + r0 * 132 + cn) = make_float2(y00, y01);
        *(float2*)(stage + r8 * 132 + cn) = make_float2(y80, y81);
        pe0 += y00 * te.x + y01 * te.y;
        pe8 += y80 * te.x + y81 * te.y;
    }
    pe0 = quad2(pe0); pe8 = quad2(pe8);
    float bt = btop[0];
    if (q == 0) {
        if (rg  < NE) edot[rg]  = pe0 + bt;
        if (rg8 < NE) edot[rg8] = pe8 + bt;
    }
    __syncthreads();
    #pragma unroll 4
    for (int rr = 0; rr < 16; rr++) {
        int r_local = rr * 8 + w;
        long e = row0 + r_local;
        if (e < NE) {
            int dst = eidx[NE + e];
            float4 v = *(float4*)(stage + r_local * 132 + lane * 4);
            red_add_v4(agge + (long)dst * H + lane * 4, v);
        }
    }
}

// -------- per layer: CSR aggregation (replaces memcpy + atomic scatter) ----
__global__ __launch_bounds__(256) void k_agg(
    const float* __restrict__ node_h, const float* __restrict__ agge,
    const float* __restrict__ ga, const float* __restrict__ gc,
    const float* __restrict__ edot, float* __restrict__ ew, float* __restrict__ agg) {
    int n = blockIdx.x * 8 + (threadIdx.x >> 5);
    int lane = threadIdx.x & 31;
    if (n >= NN) return;
    int o0 = g_off[n], deg = g_off[n + 1] - o0;
    float4 acc = *(const float4*)(agge + (long)n * H + lane * 4);
    float gcn = gc[n];
    for (int base = 0; base < deg; base += 32) {
        int m = min(32, deg - base);
        float w = 0.f; int s = 0;
        if (lane < m) {
            int e = g_se[o0 + base + lane];
            s = g_ss[o0 + base + lane];
            w = 1.f / (1.f + expf(-(ga[s] + gcn + edot[e])));
            ew[e] = w;
        }
        #pragma unroll 2
        for (int j = 0; j < m; j++) {
            float wj = __shfl_sync(0xffffffffu, w, j);
            int   sj = __shfl_sync(0xffffffffu, s, j);
            float4 h = *(const float4*)(node_h + (long)sj * H + lane * 4);
            acc.x += wj * h.x; acc.y += wj * h.y; acc.z += wj * h.z; acc.w += wj * h.w;
        }
    }
    *(float4*)(agg + (long)n * H + lane * 4) = acc;
}

// ------- node update: GEMM K=256 + bias + residual + LN + ReLU + dots ------
__global__ __launch_bounds__(256, 2) void k_mma_update(
    const float* __restrict__ node_h, float* __restrict__ nh_out,
    const float* __restrict__ agg,
    const __nv_bfloat16* __restrict__ Bhi, const __nv_bfloat16* __restrict__ Blo,
    const float* __restrict__ bg, const float* __restrict__ lns,
    const float* __restrict__ lnb, const float* __restrict__ Wtop,
    float* __restrict__ ga, float* __restrict__ gc) {
    extern __shared__ char sm[];
    const int KPAD = 136, BSPLIT = 128 * KPAD * 2;
    int tid = threadIdx.x, w = tid >> 5, lane = tid & 31;
    int q = lane & 3, g = lane >> 2;
    long row0 = (long)blockIdx.x * 128;

    long rg = row0 + w * 16 + g, rg8 = rg + 8;
    long rgl = rg < NN ? rg : NN - 1, rg8l = rg8 < NN ? rg8 : NN - 1;
    float d[16][4];
    #pragma unroll
    for (int i = 0; i < 16; i++) { d[i][0] = d[i][1] = d[i][2] = d[i][3] = 0.f; }

    const uint4* sh = (const uint4*)Bhi;
    const uint4* sl = (const uint4*)Blo;
    #pragma unroll 1
    for (int ch = 0; ch < 2; ch++) {
        for (int i = tid; i < 128 * 16; i += 256) {
            int r = i >> 4, c = i & 15;
            *(uint4*)(sm + r * 272 + c * 16) = sh[r * 32 + ch * 16 + c];
            *(uint4*)(sm + BSPLIT + r * 272 + c * 16) = sl[r * 32 + ch * 16 + c];
        }
        __syncthreads();
        const float* Asrc = ch ? agg : node_h;
        mma_mainloop<8, 136>(d, Asrc + rgl * 128, Asrc + rg8l * 128,
                             smem_u32(sm), smem_u32(sm) + BSPLIT, lane);
        __syncthreads();
    }

    float s0 = 0.f, sq0 = 0.f, s8 = 0.f, sq8 = 0.f;
    #pragma unroll
    for (int nf = 0; nf < 16; nf++) {
        int cn = nf * 8 + q * 2;
        float2 b  = *(const float2*)(bg + cn);
        float2 r0v = *(const float2*)(node_h + rgl * 128 + cn);
        float2 r8v = *(const float2*)(node_h + rg8l * 128 + cn);
        float x00 = d[nf][0] + b.x + r0v.x, x01 = d[nf][1] + b.y + r0v.y;
        float x80 = d[nf][2] + b.x + r8v.x, x81 = d[nf][3] + b.y + r8v.y;
        d[nf][0] = x00; d[nf][1] = x01; d[nf][2] = x80; d[nf][3] = x81;
        s0 += x00 + x01; sq0 += x00 * x00 + x01 * x01;
        s8 += x80 + x81; sq8 += x80 * x80 + x81 * x81;
    }
    s0 = quad2(s0); sq0 = quad2(sq0); s8 = quad2(s8); sq8 = quad2(sq8);
    float m0 = s0 * (1.f / H), m8 = s8 * (1.f / H);
    float rstd0 = rsqrtf(sq0 * (1.f / H) - m0 * m0 + 1e-6f);
    float rstd8 = rsqrtf(sq8 * (1.f / H) - m8 * m8 + 1e-6f);

    float pa0 = 0.f, pc0 = 0.f, pa8 = 0.f, pc8 = 0.f;
    #pragma unroll
    for (int nf = 0; nf < 16; nf++) {
        int cn = nf * 8 + q * 2;
        float2 sc = *(const float2*)(lns + cn);
        float2 bi = *(const float2*)(lnb + cn);
        float2 ts = *(const float2*)(Wtop + cn);
        float2 td = *(const float2*)(Wtop + 128 + cn);
        float y00 = fmaxf((d[nf][0] - m0) * rstd0 * sc.x + bi.x, 0.f);
        float y01 = fmaxf((d[nf][1] - m0) * rstd0 * sc.y + bi.y, 0.f);
        float y80 = fmaxf((d[nf][2] - m8) * rstd8 * sc.x + bi.x, 0.f);
        float y81 = fmaxf((d[nf][3] - m8) * rstd8 * sc.y + bi.y, 0.f);
        if (rg  < NN) *(float2*)(nh_out + rg  * 128 + cn) = make_float2(y00, y01);
        if (rg8 < NN) *(float2*)(nh_out + rg8 * 128 + cn) = make_float2(y80, y81);
        pa0 += y00 * ts.x + y01 * ts.y; pc0 += y00 * td.x + y01 * td.y;
        pa8 += y80 * ts.x + y81 * ts.y; pc8 += y80 * td.x + y81 * td.y;
    }
    pa0 = quad2(pa0); pc0 = quad2(pc0); pa8 = quad2(pa8); pc8 = quad2(pc8);
    if (q == 0) {
        if (rg  < NN) { ga[rg]  = pa0; gc[rg]  = pc0; }
        if (rg8 < NN) { ga[rg8] = pa8; gc[rg8] = pc8; }
    }
}

// ---------------- launch ----------------
extern "C" void kernel_launch(void* const* d_in, const int* in_sizes, int n_in,
                              void* d_out, int out_size) {
    const float* node_features = (const float*)d_in[0];
    const float* edge_features = (const float*)d_in[1];
    const int*   eidx          = (const int*)d_in[2];
    const float* W_node = (const float*)d_in[3];
    const float* b_node = (const float*)d_in[4];
    const float* W_edge = (const float*)d_in[5];
    const float* b_edge = (const float*)d_in[6];
    const float* W_gnn  = (const float*)d_in[7];
    const float* b_gnn  = (const float*)d_in[8];
    const float* W_top  = (const float*)d_in[9];
    const float* b_top  = (const float*)d_in[10];
    const float* ln_s   = (const float*)d_in[11];
    const float* ln_b   = (const float*)d_in[12];

    float *node_h, *agge, *agg, *edot, *ga, *gc;
    int* cnt;
    cudaGetSymbolAddress((void**)&node_h, g_node_h);
    cudaGetSymbolAddress((void**)&agge, g_agg_edge);
    cudaGetSymbolAddress((void**)&agg, g_agg);
    cudaGetSymbolAddress((void**)&edot, g_edot);
    cudaGetSymbolAddress((void**)&ga, g_a);
    cudaGetSymbolAddress((void**)&gc, g_c);
    cudaGetSymbolAddress((void**)&cnt, g_cnt);
    __nv_bfloat16 *Bn_hi, *Bn_lo, *Be_hi, *Be_lo, *Bg_hi, *Bg_lo;
    cudaGetSymbolAddress((void**)&Bn_hi, g_Bn_hi);
    cudaGetSymbolAddress((void**)&Bn_lo, g_Bn_lo);
    cudaGetSymbolAddress((void**)&Be_hi, g_Be_hi);
    cudaGetSymbolAddress((void**)&Be_lo, g_Be_lo);
    cudaGetSymbolAddress((void**)&Bg_hi, g_Bg_hi);
    cudaGetSymbolAddress((void**)&Bg_lo, g_Bg_lo);

    float* out_nh = (float*)d_out;
    float* out_ew = (float*)d_out + (size_t)NN * H;

    const int SM_NODE = 128 * 136 * 2 * 2;                     // 69632
    const int SM_EDGE = 128 * 72 * 2 * 2 + 128 * 132 * 4;      // 104448
    const int SM_UPD  = 128 * 136 * 2 * 2;                     // 69632
    cudaFuncSetAttribute(k_mma_node, cudaFuncAttributeMaxDynamicSharedMemorySize, SM_NODE);
    cudaFuncSetAttribute(k_mma_edge, cudaFuncAttributeMaxDynamicSharedMemorySize, SM_EDGE);
    cudaFuncSetAttribute(k_mma_update, cudaFuncAttributeMaxDynamicSharedMemorySize, SM_UPD);

    cudaMemsetAsync(agge, 0, (size_t)NN * H * sizeof(float), 0);
    cudaMemsetAsync(cnt, 0, (size_t)NN * sizeof(int), 0);
    k_prep<<<64, 256>>>(W_node, W_edge, W_gnn);

    // CSR by dst (once per launch)
    k_hist<<<(NE + 255) / 256, 256>>>(eidx);
    k_scanA<<<NB_SCAN, 256>>>();
    k_scanB<<<1, 32>>>();
    k_scanC<<<NB_SCAN, 256>>>();
    k_perm<<<(NE + 255) / 256, 256>>>(eidx);

    k_mma_node<<<(NN + 127) / 128, 256, SM_NODE>>>(node_features, Bn_hi, Bn_lo, b_node, W_top,
                                                   node_h, ga, gc);
    k_mma_edge<<<(NE + 127) / 128, 256, SM_EDGE>>>(edge_features, Be_hi, Be_lo, b_edge, W_top,
                                                   b_top, eidx, edot, agge);

    for (int i = 0; i < NL; i++) {
        k_agg<<<(NN + 7) / 8, 256>>>(node_h, agge, ga, gc, edot, out_ew, agg);
        float* nh_out = (i == NL - 1) ? out_nh : node_h;
        k_mma_update<<<(NN + 127) / 128, 256, SM_UPD>>>(node_h, nh_out, agg,
            Bg_hi + (size_t)i * 128 * 256, Bg_lo + (size_t)i * 128 * 256,
            b_gnn + (size_t)i * H, ln_s + (size_t)i * H, ln_b + (size_t)i * H, W_top, ga, gc);
    }
}

// round 7
// speedup vs baseline: 2.1237x; 1.0372x over previous
#include <cuda_runtime.h>
#include <cuda_bf16.h>
#include <stdint.h>
#include <math.h>

#define NN 50000
#define NE 200000
#define H  128
#define NL 3
#define NB_SCAN ((NN + 255) / 256)

// ---------------- scratch (device globals: allocation-free) ----------------
__device__ float g_node_h[NN * H];
__device__ float g_agg_edge[NN * H];
__device__ float g_agg[NN * H];
__device__ float g_edot[NE];
__device__ float g_a[NN];
__device__ float g_c[NN];
// CSR by dst
__device__ int g_cnt[NN];
__device__ int g_off[NN + 1];
__device__ int g_cur[NN];
__device__ int2 g_es[NE];          // (edge id, src) packed
__device__ int g_bsum[NB_SCAN];
__device__ int g_bpre[NB_SCAN];
// bf16 hi/lo weight images, transposed to [n][k] row-major
__device__ __align__(16) __nv_bfloat16 g_Bn_hi[128 * 128];
__device__ __align__(16) __nv_bfloat16 g_Bn_lo[128 * 128];
__device__ __align__(16) __nv_bfloat16 g_Be_hi[128 * 64];
__device__ __align__(16) __nv_bfloat16 g_Be_lo[128 * 64];
__device__ __align__(16) __nv_bfloat16 g_Bg_hi[NL][128 * 256];
__device__ __align__(16) __nv_bfloat16 g_Bg_lo[NL][128 * 256];

// ---------------- helpers ----------------
__device__ __forceinline__ uint32_t smem_u32(const void* p) {
    uint32_t a;
    asm("{ .reg .u64 t; cvta.to.shared.u64 t, %1; cvt.u32.u64 %0, t; }" : "=r"(a) : "l"(p));
    return a;
}
__device__ __forceinline__ float quad2(float v) {
    v += __shfl_xor_sync(0xffffffffu, v, 1);
    v += __shfl_xor_sync(0xffffffffu, v, 2);
    return v;
}
__device__ __forceinline__ void red_add_v4(float* addr, float4 v) {
    asm volatile("red.global.add.v4.f32 [%0], {%1,%2,%3,%4};"
                 :: "l"(addr), "f"(v.x), "f"(v.y), "f"(v.z), "f"(v.w) : "memory");
}
__device__ __forceinline__ uint2 split2(float2 v) {
    __nv_bfloat162 h = __floats2bfloat162_rn(v.x, v.y);
    float2 f = __bfloat1622float2(h);
    __nv_bfloat162 l = __floats2bfloat162_rn(v.x - f.x, v.y - f.y);
    return make_uint2(*(uint32_t*)&h, *(uint32_t*)&l);
}
__device__ __forceinline__ void ldsm4(uint32_t& r0, uint32_t& r1, uint32_t& r2, uint32_t& r3,
                                      uint32_t addr) {
    asm volatile("ldmatrix.sync.aligned.m8n8.x4.shared.b16 {%0,%1,%2,%3}, [%4];"
                 : "=r"(r0), "=r"(r1), "=r"(r2), "=r"(r3) : "r"(addr));
}
__device__ __forceinline__ void mma16816(float* d, const uint32_t* a, uint32_t b0, uint32_t b1) {
    asm volatile(
        "mma.sync.aligned.m16n8k16.row.col.f32.bf16.bf16.f32 "
        "{%0,%1,%2,%3}, {%4,%5,%6,%7}, {%8,%9}, {%0,%1,%2,%3};"
        : "+f"(d[0]), "+f"(d[1]), "+f"(d[2]), "+f"(d[3])
        : "r"(a[0]), "r"(a[1]), "r"(a[2]), "r"(a[3]), "r"(b0), "r"(b1));
}

template<int NKS, int KPAD>
__device__ __forceinline__ void mma_mainloop(float (*d)[4], const float* __restrict__ Ar0,
                                             const float* __restrict__ Ar8,
                                             uint32_t sBh, uint32_t sBl, int lane) {
    const int q2 = (lane & 3) * 2;
    const int nb = ((lane >> 4) << 3) + (lane & 7);
    const int kb = ((lane >> 3) & 1) << 3;
    #pragma unroll 2
    for (int ks = 0; ks < NKS; ks++) {
        int k0 = ks * 16 + q2;
        uint32_t ahi[4], alo[4];
        uint2 s;
        s = split2(*(const float2*)(Ar0 + k0));     ahi[0] = s.x; alo[0] = s.y;
        s = split2(*(const float2*)(Ar8 + k0));     ahi[1] = s.x; alo[1] = s.y;
        s = split2(*(const float2*)(Ar0 + k0 + 8)); ahi[2] = s.x; alo[2] = s.y;
        s = split2(*(const float2*)(Ar8 + k0 + 8)); ahi[3] = s.x; alo[3] = s.y;
        #pragma unroll
        for (int p = 0; p < 8; p++) {
            uint32_t off = (uint32_t)(((p * 16 + nb) * KPAD + ks * 16 + kb) * 2);
            uint32_t bh0, bh1, bh2, bh3, bl0, bl1, bl2, bl3;
            ldsm4(bh0, bh1, bh2, bh3, sBh + off);
            ldsm4(bl0, bl1, bl2, bl3, sBl + off);
            mma16816(d[2 * p],     ahi, bh0, bh1);
            mma16816(d[2 * p],     ahi, bl0, bl1);
            mma16816(d[2 * p],     alo, bh0, bh1);
            mma16816(d[2 * p + 1], ahi, bh2, bh3);
            mma16816(d[2 * p + 1], ahi, bl2, bl3);
            mma16816(d[2 * p + 1], alo, bh2, bh3);
        }
    }
}

// ---------------- weight prep ----------------
__global__ void k_prep(const float* __restrict__ Wn, const float* __restrict__ We,
                       const float* __restrict__ Wg) {
    int stride = gridDim.x * blockDim.x;
    int t0 = blockIdx.x * blockDim.x + threadIdx.x;
    for (int i = t0; i < 128 * 128; i += stride) {
        int k = i >> 7, n = i & 127;
        float w = Wn[i];
        __nv_bfloat16 hi = __float2bfloat16(w);
        g_Bn_hi[n * 128 + k] = hi;
        g_Bn_lo[n * 128 + k] = __float2bfloat16(w - __bfloat162float(hi));
    }
    for (int i = t0; i < 64 * 128; i += stride) {
        int k = i >> 7, n = i & 127;
        float w = We[i];
        __nv_bfloat16 hi = __float2bfloat16(w);
        g_Be_hi[n * 64 + k] = hi;
        g_Be_lo[n * 64 + k] = __float2bfloat16(w - __bfloat162float(hi));
    }
    for (int i = t0; i < NL * 256 * 128; i += stride) {
        int l = i / (256 * 128);
        int j = i - l * 256 * 128;
        int k = j >> 7, n = j & 127;
        float w = Wg[i];
        __nv_bfloat16 hi = __float2bfloat16(w);
        g_Bg_hi[l][n * 256 + k] = hi;
        g_Bg_lo[l][n * 256 + k] = __float2bfloat16(w - __bfloat162float(hi));
    }
}

// ---------------- CSR build ----------------
__global__ void k_hist(const int* __restrict__ eidx) {
    int e = blockIdx.x * blockDim.x + threadIdx.x;
    if (e < NE) atomicAdd(&g_cnt[eidx[NE + e]], 1);
}
__global__ void k_scanA() {   // per-block sums of g_cnt
    __shared__ int s[256];
    int i = blockIdx.x * 256 + threadIdx.x;
    int v = (i < NN) ? g_cnt[i] : 0;
    s[threadIdx.x] = v;
    __syncthreads();
    for (int o = 128; o > 0; o >>= 1) {
        if (threadIdx.x < o) s[threadIdx.x] += s[threadIdx.x + o];
        __syncthreads();
    }
    if (threadIdx.x == 0) g_bsum[blockIdx.x] = s[0];
}
__global__ void k_scanB() {   // parallel exclusive scan of NB_SCAN block sums
    __shared__ int warp_tot[8];
    int tid = threadIdx.x, lane = tid & 31, w = tid >> 5;
    int v = (tid < NB_SCAN) ? g_bsum[tid] : 0;
    int x = v;
    #pragma unroll
    for (int o = 1; o < 32; o <<= 1) {
        int t = __shfl_up_sync(0xffffffffu, x, o);
        if (lane >= o) x += t;
    }
    if (lane == 31) warp_tot[w] = x;
    __syncthreads();
    if (w == 0) {
        int t = (lane < 8) ? warp_tot[lane] : 0;
        #pragma unroll
        for (int o = 1; o < 8; o <<= 1) {
            int u = __shfl_up_sync(0xffffffffu, t, o);
            if (lane >= o) t += u;
        }
        if (lane < 8) warp_tot[lane] = t;
    }
    __syncthreads();
    int base = (w > 0) ? warp_tot[w - 1] : 0;
    if (tid < NB_SCAN) g_bpre[tid] = base + x - v;
}
__global__ void k_scanC() {   // per-element exclusive scan + base
    __shared__ int s[256];
    int i = blockIdx.x * 256 + threadIdx.x;
    int v = (i < NN) ? g_cnt[i] : 0;
    s[threadIdx.x] = v;
    __syncthreads();
    for (int o = 1; o < 256; o <<= 1) {
        int t = (threadIdx.x >= o) ? s[threadIdx.x - o] : 0;
        __syncthreads();
        s[threadIdx.x] += t;
        __syncthreads();
    }
    if (i < NN) {
        int excl = g_bpre[blockIdx.x] + s[threadIdx.x] - v;
        g_off[i] = excl;
        g_cur[i] = excl;
        if (i == NN - 1) g_off[NN] = excl + v;
    }
}
__global__ void k_perm(const int* __restrict__ eidx) {
    int e = blockIdx.x * blockDim.x + threadIdx.x;
    if (e < NE) {
        int d = eidx[NE + e];
        int pos = atomicAdd(&g_cur[d], 1);
        g_es[pos] = make_int2(e, eidx[e]);
    }
}

// ---------------- node embed ----------------
__global__ __launch_bounds__(256, 2) void k_mma_node(
    const float* __restrict__ A, const __nv_bfloat16* __restrict__ Bhi,
    const __nv_bfloat16* __restrict__ Blo, const float* __restrict__ bn,
    const float* __restrict__ Wtop, float* __restrict__ node_h,
    float* __restrict__ ga, float* __restrict__ gc) {
    extern __shared__ char sm[];
    const int KPAD = 136, BSPLIT = 128 * KPAD * 2;
    int tid = threadIdx.x, w = tid >> 5, lane = tid & 31;
    int q = lane & 3, g = lane >> 2;
    long row0 = (long)blockIdx.x * 128;

    const uint4* sh = (const uint4*)Bhi;
    const uint4* sl = (const uint4*)Blo;
    for (int i = tid; i < 128 * 16; i += 256) {
        int r = i >> 4, c = i & 15;
        *(uint4*)(sm + r * 272 + c * 16) = sh[r * 16 + c];
        *(uint4*)(sm + BSPLIT + r * 272 + c * 16) = sl[r * 16 + c];
    }
    __syncthreads();

    long rg = row0 + w * 16 + g, rg8 = rg + 8;
    long rgl = rg < NN ? rg : NN - 1, rg8l = rg8 < NN ? rg8 : NN - 1;
    float d[16][4];
    #pragma unroll
    for (int i = 0; i < 16; i++) { d[i][0] = d[i][1] = d[i][2] = d[i][3] = 0.f; }
    mma_mainloop<8, 136>(d, A + rgl * 128, A + rg8l * 128,
                         smem_u32(sm), smem_u32(sm) + BSPLIT, lane);

    float pa0 = 0.f, pc0 = 0.f, pa8 = 0.f, pc8 = 0.f;
    #pragma unroll
    for (int nf = 0; nf < 16; nf++) {
        int cn = nf * 8 + q * 2;
        float2 b  = *(const float2*)(bn + cn);
        float2 ts = *(const float2*)(Wtop + cn);
        float2 td = *(const float2*)(Wtop + 128 + cn);
        float y00 = d[nf][0] + b.x, y01 = d[nf][1] + b.y;
        float y80 = d[nf][2] + b.x, y81 = d[nf][3] + b.y;
        if (rg  < NN) *(float2*)(node_h + rg  * 128 + cn) = make_float2(y00, y01);
        if (rg8 < NN) *(float2*)(node_h + rg8 * 128 + cn) = make_float2(y80, y81);
        pa0 += y00 * ts.x + y01 * ts.y; pc0 += y00 * td.x + y01 * td.y;
        pa8 += y80 * ts.x + y81 * ts.y; pc8 += y80 * td.x + y81 * td.y;
    }
    pa0 = quad2(pa0); pc0 = quad2(pc0); pa8 = quad2(pa8); pc8 = quad2(pc8);
    if (q == 0) {
        if (rg  < NN) { ga[rg]  = pa0; gc[rg]  = pc0; }
        if (rg8 < NN) { ga[rg8] = pa8; gc[rg8] = pc8; }
    }
}

// ---------------- edge embed (fused): edot + agge scatter ------------------
__global__ __launch_bounds__(256, 2) void k_mma_edge(
    const float* __restrict__ A, const __nv_bfloat16* __restrict__ Bhi,
    const __nv_bfloat16* __restrict__ Blo, const float* __restrict__ be,
    const float* __restrict__ Wtop, const float* __restrict__ btop,
    const int* __restrict__ eidx, float* __restrict__ edot, float* __restrict__ agge) {
    extern __shared__ char sm[];
    const int KPAD = 72, BSPLIT = 128 * KPAD * 2;
    const int OFF_STAGE = 2 * BSPLIT;
    float* stage = (float*)(sm + OFF_STAGE);   // [128][132]
    int tid = threadIdx.x, w = tid >> 5, lane = tid & 31;
    int q = lane & 3, g = lane >> 2;
    long row0 = (long)blockIdx.x * 128;

    const uint4* sh = (const uint4*)Bhi;
    const uint4* sl = (const uint4*)Blo;
    for (int i = tid; i < 128 * 8; i += 256) {
        int r = i >> 3, c = i & 7;
        *(uint4*)(sm + r * 144 + c * 16) = sh[r * 8 + c];
        *(uint4*)(sm + BSPLIT + r * 144 + c * 16) = sl[r * 8 + c];
    }
    __syncthreads();

    long rg = row0 + w * 16 + g, rg8 = rg + 8;
    long rgl = rg < NE ? rg : NE - 1, rg8l = rg8 < NE ? rg8 : NE - 1;
    float d[16][4];
    #pragma unroll
    for (int i = 0; i < 16; i++) { d[i][0] = d[i][1] = d[i][2] = d[i][3] = 0.f; }
    mma_mainloop<4, 72>(d, A + rgl * 64, A + rg8l * 64,
                        smem_u32(sm), smem_u32(sm) + BSPLIT, lane);

    int r0 = w * 16 + g, r8 = r0 + 8;
    float pe0 = 0.f, pe8 = 0.f;
    #pragma unroll
    for (int nf = 0; nf < 16; nf++) {
        int cn = nf * 8 + q * 2;
        float2 b  = *(const float2*)(be + cn);
        float2 te = *(const float2*)(Wtop + 256 + cn);
        float y00 = d[nf][0] + b.x, y01 = d[nf][1] + b.y;
        float y80 = d[nf][2] + b.x, y81 = d[nf][3] + b.y;
        *(float2*)(stage + r0 * 132 + cn) = make_float2(y00, y01);
        *(float2*)(stage + r8 * 132 + cn) = make_float2(y80, y81);
        pe0 += y00 * te.x + y01 * te.y;
        pe8 += y80 * te.x + y81 * te.y;
    }
    pe0 = quad2(pe0); pe8 = quad2(pe8);
    float bt = btop[0];
    if (q == 0) {
        if (rg  < NE) edot[rg]  = pe0 + bt;
        if (rg8 < NE) edot[rg8] = pe8 + bt;
    }
    __syncthreads();
    #pragma unroll 4
    for (int rr = 0; rr < 16; rr++) {
        int r_local = rr * 8 + w;
        long e = row0 + r_local;
        if (e < NE) {
            int dst = eidx[NE + e];
            float4 v = *(float4*)(stage + r_local * 132 + lane * 4);
            red_add_v4(agge + (long)dst * H + lane * 4, v);
        }
    }
}

// -------- per layer: CSR aggregation ----
template<bool WEW>
__global__ __launch_bounds__(256) void k_agg(
    const float* __restrict__ node_h, const float* __restrict__ agge,
    const float* __restrict__ ga, const float* __restrict__ gc,
    const float* __restrict__ edot, float* __restrict__ ew, float* __restrict__ agg) {
    int n = blockIdx.x * 8 + (threadIdx.x >> 5);
    int lane = threadIdx.x & 31;
    if (n >= NN) return;
    int o0 = g_off[n], deg = g_off[n + 1] - o0;
    float4 acc = *(const float4*)(agge + (long)n * H + lane * 4);
    float gcn = gc[n];
    for (int base = 0; base < deg; base += 32) {
        int m = min(32, deg - base);
        float w = 0.f; int s = 0;
        if (lane < m) {
            int2 es = g_es[o0 + base + lane];
            s = es.y;
            w = __fdividef(1.f, 1.f + __expf(-(ga[s] + gcn + edot[es.x])));
            if (WEW) ew[es.x] = w;
        }
        #pragma unroll 2
        for (int j = 0; j < m; j++) {
            float wj = __shfl_sync(0xffffffffu, w, j);
            int   sj = __shfl_sync(0xffffffffu, s, j);
            float4 h = *(const float4*)(node_h + (long)sj * H + lane * 4);
            acc.x += wj * h.x; acc.y += wj * h.y; acc.z += wj * h.z; acc.w += wj * h.w;
        }
    }
    *(float4*)(agg + (long)n * H + lane * 4) = acc;
}

// ------- node update: GEMM K=256 + bias + residual + LN + ReLU + dots ------
__global__ __launch_bounds__(256, 2) void k_mma_update(
    const float* __restrict__ node_h, float* __restrict__ nh_out,
    const float* __restrict__ agg,
    const __nv_bfloat16* __restrict__ Bhi, const __nv_bfloat16* __restrict__ Blo,
    const float* __restrict__ bg, const float* __restrict__ lns,
    const float* __restrict__ lnb, const float* __restrict__ Wtop,
    float* __restrict__ ga, float* __restrict__ gc) {
    extern __shared__ char sm[];
    const int KPAD = 136, BSPLIT = 128 * KPAD * 2;
    int tid = threadIdx.x, w = tid >> 5, lane = tid & 31;
    int q = lane & 3, g = lane >> 2;
    long row0 = (long)blockIdx.x * 128;

    long rg = row0 + w * 16 + g, rg8 = rg + 8;
    long rgl = rg < NN ? rg : NN - 1, rg8l = rg8 < NN ? rg8 : NN - 1;
    float d[16][4];
    #pragma unroll
    for (int i = 0; i < 16; i++) { d[i][0] = d[i][1] = d[i][2] = d[i][3] = 0.f; }

    const uint4* sh = (const uint4*)Bhi;
    const uint4* sl = (const uint4*)Blo;
    #pragma unroll 1
    for (int ch = 0; ch < 2; ch++) {
        for (int i = tid; i < 128 * 16; i += 256) {
            int r = i >> 4, c = i & 15;
            *(uint4*)(sm + r * 272 + c * 16) = sh[r * 32 + ch * 16 + c];
            *(uint4*)(sm + BSPLIT + r * 272 + c * 16) = sl[r * 32 + ch * 16 + c];
        }
        __syncthreads();
        const float* Asrc = ch ? agg : node_h;
        mma_mainloop<8, 136>(d, Asrc + rgl * 128, Asrc + rg8l * 128,
                             smem_u32(sm), smem_u32(sm) + BSPLIT, lane);
        __syncthreads();
    }

    float s0 = 0.f, sq0 = 0.f, s8 = 0.f, sq8 = 0.f;
    #pragma unroll
    for (int nf = 0; nf < 16; nf++) {
        int cn = nf * 8 + q * 2;
        float2 b  = *(const float2*)(bg + cn);
        float2 r0v = *(const float2*)(node_h + rgl * 128 + cn);
        float2 r8v = *(const float2*)(node_h + rg8l * 128 + cn);
        float x00 = d[nf][0] + b.x + r0v.x, x01 = d[nf][1] + b.y + r0v.y;
        float x80 = d[nf][2] + b.x + r8v.x, x81 = d[nf][3] + b.y + r8v.y;
        d[nf][0] = x00; d[nf][1] = x01; d[nf][2] = x80; d[nf][3] = x81;
        s0 += x00 + x01; sq0 += x00 * x00 + x01 * x01;
        s8 += x80 + x81; sq8 += x80 * x80 + x81 * x81;
    }
    s0 = quad2(s0); sq0 = quad2(sq0); s8 = quad2(s8); sq8 = quad2(sq8);
    float m0 = s0 * (1.f / H), m8 = s8 * (1.f / H);
    float rstd0 = rsqrtf(sq0 * (1.f / H) - m0 * m0 + 1e-6f);
    float rstd8 = rsqrtf(sq8 * (1.f / H) - m8 * m8 + 1e-6f);

    float pa0 = 0.f, pc0 = 0.f, pa8 = 0.f, pc8 = 0.f;
    #pragma unroll
    for (int nf = 0; nf < 16; nf++) {
        int cn = nf * 8 + q * 2;
        float2 sc = *(const float2*)(lns + cn);
        float2 bi = *(const float2*)(lnb + cn);
        float2 ts = *(const float2*)(Wtop + cn);
        float2 td = *(const float2*)(Wtop + 128 + cn);
        float y00 = fmaxf((d[nf][0] - m0) * rstd0 * sc.x + bi.x, 0.f);
        float y01 = fmaxf((d[nf][1] - m0) * rstd0 * sc.y + bi.y, 0.f);
        float y80 = fmaxf((d[nf][2] - m8) * rstd8 * sc.x + bi.x, 0.f);
        float y81 = fmaxf((d[nf][3] - m8) * rstd8 * sc.y + bi.y, 0.f);
        if (rg  < NN) *(float2*)(nh_out + rg  * 128 + cn) = make_float2(y00, y01);
        if (rg8 < NN) *(float2*)(nh_out + rg8 * 128 + cn) = make_float2(y80, y81);
        pa0 += y00 * ts.x + y01 * ts.y; pc0 += y00 * td.x + y01 * td.y;
        pa8 += y80 * ts.x + y81 * ts.y; pc8 += y80 * td.x + y81 * td.y;
    }
    pa0 = quad2(pa0); pc0 = quad2(pc0); pa8 = quad2(pa8); pc8 = quad2(pc8);
    if (q == 0) {
        if (rg  < NN) { ga[rg]  = pa0; gc[rg]  = pc0; }
        if (rg8 < NN) { ga[rg8] = pa8; gc[rg8] = pc8; }
    }
}

// ---------------- launch ----------------
extern "C" void kernel_launch(void* const* d_in, const int* in_sizes, int n_in,
                              void* d_out, int out_size) {
    const float* node_features = (const float*)d_in[0];
    const float* edge_features = (const float*)d_in[1];
    const int*   eidx          = (const int*)d_in[2];
    const float* W_node = (const float*)d_in[3];
    const float* b_node = (const float*)d_in[4];
    const float* W_edge = (const float*)d_in[5];
    const float* b_edge = (const float*)d_in[6];
    const float* W_gnn  = (const float*)d_in[7];
    const float* b_gnn  = (const float*)d_in[8];
    const float* W_top  = (const float*)d_in[9];
    const float* b_top  = (const float*)d_in[10];
    const float* ln_s   = (const float*)d_in[11];
    const float* ln_b   = (const float*)d_in[12];

    float *node_h, *agge, *agg, *edot, *ga, *gc;
    int* cnt;
    cudaGetSymbolAddress((void**)&node_h, g_node_h);
    cudaGetSymbolAddress((void**)&agge, g_agg_edge);
    cudaGetSymbolAddress((void**)&agg, g_agg);
    cudaGetSymbolAddress((void**)&edot, g_edot);
    cudaGetSymbolAddress((void**)&ga, g_a);
    cudaGetSymbolAddress((void**)&gc, g_c);
    cudaGetSymbolAddress((void**)&cnt, g_cnt);
    __nv_bfloat16 *Bn_hi, *Bn_lo, *Be_hi, *Be_lo, *Bg_hi, *Bg_lo;
    cudaGetSymbolAddress((void**)&Bn_hi, g_Bn_hi);
    cudaGetSymbolAddress((void**)&Bn_lo, g_Bn_lo);
    cudaGetSymbolAddress((void**)&Be_hi, g_Be_hi);
    cudaGetSymbolAddress((void**)&Be_lo, g_Be_lo);
    cudaGetSymbolAddress((void**)&Bg_hi, g_Bg_hi);
    cudaGetSymbolAddress((void**)&Bg_lo, g_Bg_lo);

    float* out_nh = (float*)d_out;
    float* out_ew = (float*)d_out + (size_t)NN * H;

    const int SM_NODE = 128 * 136 * 2 * 2;                     // 69632
    const int SM_EDGE = 128 * 72 * 2 * 2 + 128 * 132 * 4;      // 104448
    const int SM_UPD  = 128 * 136 * 2 * 2;                     // 69632
    cudaFuncSetAttribute(k_mma_node, cudaFuncAttributeMaxDynamicSharedMemorySize, SM_NODE);
    cudaFuncSetAttribute(k_mma_edge, cudaFuncAttributeMaxDynamicSharedMemorySize, SM_EDGE);
    cudaFuncSetAttribute(k_mma_update, cudaFuncAttributeMaxDynamicSharedMemorySize, SM_UPD);

    cudaMemsetAsync(agge, 0, (size_t)NN * H * sizeof(float), 0);
    cudaMemsetAsync(cnt, 0, (size_t)NN * sizeof(int), 0);
    k_prep<<<64, 256>>>(W_node, W_edge, W_gnn);

    // CSR by dst (once per launch)
    k_hist<<<(NE + 255) / 256, 256>>>(eidx);
    k_scanA<<<NB_SCAN, 256>>>();
    k_scanB<<<1, 256>>>();
    k_scanC<<<NB_SCAN, 256>>>();
    k_perm<<<(NE + 255) / 256, 256>>>(eidx);

    k_mma_node<<<(NN + 127) / 128, 256, SM_NODE>>>(node_features, Bn_hi, Bn_lo, b_node, W_top,
                                                   node_h, ga, gc);
    k_mma_edge<<<(NE + 127) / 128, 256, SM_EDGE>>>(edge_features, Be_hi, Be_lo, b_edge, W_top,
                                                   b_top, eidx, edot, agge);

    for (int i = 0; i < NL; i++) {
        if (i == NL - 1)
            k_agg<true><<<(NN + 7) / 8, 256>>>(node_h, agge, ga, gc, edot, out_ew, agg);
        else
            k_agg<false><<<(NN + 7) / 8, 256>>>(node_h, agge, ga, gc, edot, out_ew, agg);
        float* nh_out = (i == NL - 1) ? out_nh : node_h;
        k_mma_update<<<(NN + 127) / 128, 256, SM_UPD>>>(node_h, nh_out, agg,
            Bg_hi + (size_t)i * 128 * 256, Bg_lo + (size_t)i * 128 * 256,
            b_gnn + (size_t)i * H, ln_s + (size_t)i * H, ln_b + (size_t)i * H, W_top, ga, gc);
    }
}